// round 10
// baseline (speedup 1.0000x reference)
#include <cuda_runtime.h>
#include <cuda_bf16.h>

#define N_NODES 50000
#define E_EDGES 800000
#define IN_C    16
#define HDIM    64
#define HH      32
#define NLAYERS 3
#define FULL    0xffffffffu

typedef unsigned long long u64;

// Scratch (device globals; float4 for 16B alignment)
__device__ float  g_h[N_NODES * HDIM];   // row-major [n][64]
__device__ float4 g_p4[N_NODES * 8];     // row-major [n][32]
__device__ float4 g_q4[N_NODES * 8];     // row-major [n][32]
__device__ float  g_cnt[N_NODES];

// Packed k-pair weights: (w[2kp][j], w[2kp+1][j]) as u64
__device__ u64 g_w2p[NLAYERS * 16 * 64]; // [l][kp<16][j<64]
__device__ u64 g_w1p[NLAYERS * 32 * 32]; // [l][kp<32][j<32] (rows 0..63 of w1)
__device__ u64 g_dw1p[32 * 32];
__device__ u64 g_vw1p[32 * 32];

__device__ __forceinline__ u64 pack2(float lo, float hi) {
    u64 r;
    asm("mov.b64 %0, {%1, %2};" : "=l"(r) : "r"(__float_as_uint(lo)), "r"(__float_as_uint(hi)));
    return r;
}
__device__ __forceinline__ void unpack2(u64 v, float& lo, float& hi) {
    unsigned a, b;
    asm("mov.b64 {%0, %1}, %2;" : "=r"(a), "=r"(b) : "l"(v));
    lo = __uint_as_float(a); hi = __uint_as_float(b);
}
__device__ __forceinline__ u64 fma2(u64 a, u64 b, u64 c) {
    u64 d;
    asm("fma.rn.f32x2 %0, %1, %2, %3;" : "=l"(d) : "l"(a), "l"(b), "l"(c));
    return d;
}
__device__ __forceinline__ float pairsum(u64 v) {
    float lo, hi; unpack2(v, lo, hi); return lo + hi;
}
__device__ __forceinline__ void red_add_v4(float* ptr, float4 v) {
    asm volatile("red.global.add.v4.f32 [%0], {%1,%2,%3,%4};"
                 :: "l"(ptr), "f"(v.x), "f"(v.y), "f"(v.z), "f"(v.w) : "memory");
}

// ---------------- weight pack (once per run) ----------------
__global__ void pack_kernel(const float* __restrict__ mlp_w1,
                            const float* __restrict__ mlp_w2,
                            const float* __restrict__ dw1,
                            const float* __restrict__ vw1)
{
    int idx = blockIdx.x * blockDim.x + threadIdx.x;
    if (idx < 3072) {                       // w2p: 3 * 16 * 64
        int l = idx / 1024, r = idx % 1024, kp = r / 64, j = r % 64;
        const float* w2 = mlp_w2 + (size_t)l * 32 * 64;
        g_w2p[idx] = pack2(w2[(2 * kp) * 64 + j], w2[(2 * kp + 1) * 64 + j]);
    } else if (idx < 6144) {                // w1p: 3 * 32 * 32
        int r2 = idx - 3072;
        int l = r2 / 1024, r = r2 % 1024, kp = r / 32, j = r % 32;
        const float* w1 = mlp_w1 + (size_t)l * 67 * 32;
        g_w1p[r2] = pack2(w1[(2 * kp) * 32 + j], w1[(2 * kp + 1) * 32 + j]);
    } else if (idx < 7168) {                // dw1p: 32 * 32
        int r = idx - 6144, kp = r / 32, j = r % 32;
        g_dw1p[r] = pack2(dw1[(2 * kp) * 32 + j], dw1[(2 * kp + 1) * 32 + j]);
    } else if (idx < 8192) {                // vw1p
        int r = idx - 7168, kp = r / 32, j = r % 32;
        g_vw1p[r] = pack2(vw1[(2 * kp) * 32 + j], vw1[(2 * kp + 1) * 32 + j]);
    }
}

// ---------------- encoder (R4, proven): h + p0 + zero q/cnt ----------------
__global__ __launch_bounds__(256) void encoder_kernel(
    const float* __restrict__ x,  const float* __restrict__ w,
    const float* __restrict__ b,  const float* __restrict__ g,
    const float* __restrict__ beta,
    const float* __restrict__ w1, const float* __restrict__ b1)
{
    int warp = (blockIdx.x * blockDim.x + threadIdx.x) >> 5;
    int lane = threadIdx.x & 31;
    int n0   = warp * 4;
    if (n0 >= N_NODES) return;

    float* g_p = (float*)g_p4;
    float* g_q = (float*)g_q4;

    float xv[4], a0[4], a1[4];
#pragma unroll
    for (int i = 0; i < 4; i++) {
        xv[i] = (lane < IN_C) ? x[(n0 + i) * IN_C + lane] : 0.0f;
        a0[i] = __ldg(&b[lane]);
        a1[i] = __ldg(&b[lane + 32]);
    }
#pragma unroll
    for (int k = 0; k < IN_C; k++) {
        float w0 = __ldg(&w[k * HDIM + lane]);
        float w1v = __ldg(&w[k * HDIM + 32 + lane]);
#pragma unroll
        for (int i = 0; i < 4; i++) {
            float xk = __shfl_sync(FULL, xv[i], k);
            a0[i] = fmaf(xk, w0, a0[i]);
            a1[i] = fmaf(xk, w1v, a1[i]);
        }
    }
    float gl = __ldg(&g[lane]), gh = __ldg(&g[lane + 32]);
    float bl = __ldg(&beta[lane]), bh = __ldg(&beta[lane + 32]);
    float h0[4], h1[4];
#pragma unroll
    for (int i = 0; i < 4; i++) {
        float s1 = a0[i] + a1[i], s2 = a0[i] * a0[i] + a1[i] * a1[i];
#pragma unroll
        for (int o = 16; o; o >>= 1) {
            s1 += __shfl_xor_sync(FULL, s1, o);
            s2 += __shfl_xor_sync(FULL, s2, o);
        }
        float mu  = s1 * (1.0f / 64.0f);
        float var = s2 * (1.0f / 64.0f) - mu * mu;
        float rs  = rsqrtf(var + 1e-5f);
        h0[i] = fmaxf(fmaf((a0[i] - mu) * rs, gl, bl), 0.0f);
        h1[i] = fmaxf(fmaf((a1[i] - mu) * rs, gh, bh), 0.0f);
        g_h[(n0 + i) * HDIM + lane]      = h0[i];
        g_h[(n0 + i) * HDIM + 32 + lane] = h1[i];
    }
    float acc[4];
#pragma unroll
    for (int i = 0; i < 4; i++) acc[i] = __ldg(&b1[lane]);
#pragma unroll
    for (int k = 0; k < 32; k++) {
        float wk = __ldg(&w1[k * HH + lane]);
#pragma unroll
        for (int i = 0; i < 4; i++)
            acc[i] = fmaf(__shfl_sync(FULL, h0[i], k), wk, acc[i]);
    }
#pragma unroll
    for (int k = 0; k < 32; k++) {
        float wk = __ldg(&w1[(32 + k) * HH + lane]);
#pragma unroll
        for (int i = 0; i < 4; i++)
            acc[i] = fmaf(__shfl_sync(FULL, h1[i], k), wk, acc[i]);
    }
#pragma unroll
    for (int i = 0; i < 4; i++) {
        g_p[(n0 + i) * HH + lane] = acc[i];
        g_q[(n0 + i) * HH + lane] = 0.0f;
    }
    if (lane < 4) g_cnt[n0 + lane] = 0.0f;
}

// ---------------- edge kernel (R4, proven; COUNT folds in-degree) ----------------
template<bool COUNT>
__global__ __launch_bounds__(256) void edge_kernel(
    const int* __restrict__ ei, const float* __restrict__ ea,
    const float* __restrict__ w1)
{
    int idx = blockIdx.x * blockDim.x + threadIdx.x;
    int e = idx >> 3, quad = idx & 7;
    if (e >= E_EDGES) return;

    int src = __ldg(&ei[e]);
    int dst = __ldg(&ei[E_EDGES + e]);
    float e0 = __ldg(&ea[e * 3 + 0]);
    float e1 = __ldg(&ea[e * 3 + 1]);
    float e2 = __ldg(&ea[e * 3 + 2]);

    float4 p = __ldg(&g_p4[src * 8 + quad]);
    const float4* W = (const float4*)(w1 + 64 * HH);
    float4 wa = __ldg(&W[quad]);
    float4 wb = __ldg(&W[8 + quad]);
    float4 wc = __ldg(&W[16 + quad]);

    float4 v;
    v.x = fmaxf(fmaf(e2, wc.x, fmaf(e1, wb.x, fmaf(e0, wa.x, p.x))), 0.0f);
    v.y = fmaxf(fmaf(e2, wc.y, fmaf(e1, wb.y, fmaf(e0, wa.y, p.y))), 0.0f);
    v.z = fmaxf(fmaf(e2, wc.z, fmaf(e1, wb.z, fmaf(e0, wa.z, p.z))), 0.0f);
    v.w = fmaxf(fmaf(e2, wc.w, fmaf(e1, wb.w, fmaf(e0, wa.w, p.w))), 0.0f);

    red_add_v4((float*)&g_q4[dst * 8 + quad], v);
    if (COUNT && quad == 0) atomicAdd(&g_cnt[dst], 1.0f);
}

// ---- stage-2 + mean + residual + LN; f32x2, register-capped; LAST fuses heads ----
template<bool LAST>
__global__ __launch_bounds__(256, 6) void node_agg_kernel(
    int layer,
    const float* __restrict__ b2,
    const float* __restrict__ g,   const float* __restrict__ beta,
    const float* __restrict__ b1n,
    const float* __restrict__ db1, const float* __restrict__ dw2,
    const float* __restrict__ db2, const float* __restrict__ vb1,
    const float* __restrict__ vw2, const float* __restrict__ vb2,
    float* __restrict__ out)
{
    __shared__ __align__(16) float qbuf[32 * 36];   // [node][k<32], stride 36
    __shared__ __align__(16) float hbuf[32 * 68];   // [node][k<64], stride 68
    int t = threadIdx.x, w = t >> 5, lane = t & 31;
    int n0 = blockIdx.x * 32;
    int rem = N_NODES - n0; if (rem > 32) rem = 32;

    // stage q (direct padded copy); zero q behind us
    {
        int nl = t >> 3, k0 = (t & 7) << 2;
        float4 v = make_float4(0.f, 0.f, 0.f, 0.f);
        float4* qp = (float4*)g_q4 + (size_t)n0 * 8 + t;
        if (nl < rem) { v = *qp; *qp = make_float4(0.f, 0.f, 0.f, 0.f); }
        *(float4*)&qbuf[nl * 36 + k0] = v;
    }
    __syncthreads();

    int nb = w * 4;   // this warp's nodes: n0+nb .. n0+nb+3

    // stage-2 GEMV via f32x2, 2-node chunks executed SEQUENTIALLY
    float o0[4], o1[4];
    {
        const u64* w2p = g_w2p + (size_t)layer * 16 * 64;
#pragma unroll 1
        for (int c = 0; c < 2; c++) {
            u64 aL0 = 0, aH0 = 0, aL1 = 0, aH1 = 0;
            const float* qa = &qbuf[(nb + 2 * c) * 36];
            const float* qb = &qbuf[(nb + 2 * c + 1) * 36];
#pragma unroll 4
            for (int kp = 0; kp < 16; kp++) {
                u64 q0 = *(const u64*)(qa + 2 * kp);
                u64 q1 = *(const u64*)(qb + 2 * kp);
                u64 wL = __ldg(&w2p[kp * 64 + lane]);
                u64 wH = __ldg(&w2p[kp * 64 + 32 + lane]);
                aL0 = fma2(q0, wL, aL0); aH0 = fma2(q0, wH, aH0);
                aL1 = fma2(q1, wL, aL1); aH1 = fma2(q1, wH, aH1);
            }
            o0[2 * c]     = pairsum(aL0); o1[2 * c]     = pairsum(aH0);
            o0[2 * c + 1] = pairsum(aL1); o1[2 * c + 1] = pairsum(aH1);
        }
    }
    float b2l = __ldg(&b2[lane]),  b2h = __ldg(&b2[32 + lane]);
    float gl  = __ldg(&g[lane]),   gh  = __ldg(&g[lane + 32]);
    float bl  = __ldg(&beta[lane]), bh = __ldg(&beta[lane + 32]);

#pragma unroll
    for (int i = 0; i < 4; i++) {
        int n = n0 + nb + i;
        bool act = (nb + i) < rem;
        float c   = act ? g_cnt[n] : 0.f;
        float inv = (c > 0.f) ? (1.f / c) : 0.f;
        float has = (c > 0.f) ? 1.f : 0.f;
        float hh0 = act ? g_h[(size_t)n * HDIM + lane] : 0.f;
        float hh1 = act ? g_h[(size_t)n * HDIM + 32 + lane] : 0.f;
        float a0 = hh0 + o0[i] * inv + has * b2l;
        float a1 = hh1 + o1[i] * inv + has * b2h;
        float s1 = a0 + a1, s2 = a0 * a0 + a1 * a1;
#pragma unroll
        for (int o = 16; o; o >>= 1) {
            s1 += __shfl_xor_sync(FULL, s1, o);
            s2 += __shfl_xor_sync(FULL, s2, o);
        }
        float mu  = s1 * (1.f / 64.f);
        float var = s2 * (1.f / 64.f) - mu * mu;
        float rs  = rsqrtf(var + 1e-5f);
        float h0 = fmaf((a0 - mu) * rs, gl, bl);
        float h1 = fmaf((a1 - mu) * rs, gh, bh);
        if (!LAST && act) {
            g_h[(size_t)n * HDIM + lane]      = h0;
            g_h[(size_t)n * HDIM + 32 + lane] = h1;
        }
        // warp-local h buffer ([node][k] layout)
        hbuf[(nb + i) * 68 + lane]      = h0;
        hbuf[(nb + i) * 68 + 32 + lane] = h1;
    }
    __syncwarp();

    if (!LAST) {
        // p_next = h_new @ W1n[:64] + b1n; 2-node chunks, sequential
        const u64* w1p = g_w1p + (size_t)(layer + 1) * 32 * 32;
        float bb = __ldg(&b1n[lane]);
        float* gp = (float*)g_p4;
#pragma unroll 1
        for (int c = 0; c < 2; c++) {
            u64 a0 = 0, a1 = 0;
            const float* ha = &hbuf[(nb + 2 * c) * 68];
            const float* hb = &hbuf[(nb + 2 * c + 1) * 68];
#pragma unroll 4
            for (int kp = 0; kp < 32; kp++) {
                u64 h0v = *(const u64*)(ha + 2 * kp);
                u64 h1v = *(const u64*)(hb + 2 * kp);
                u64 wv = __ldg(&w1p[kp * 32 + lane]);
                a0 = fma2(h0v, wv, a0);
                a1 = fma2(h1v, wv, a1);
            }
            if ((nb + 2 * c) < rem)
                gp[(size_t)(n0 + nb + 2 * c) * HH + lane] = pairsum(a0) + bb;
            if ((nb + 2 * c + 1) < rem)
                gp[(size_t)(n0 + nb + 2 * c + 1) * HH + lane] = pairsum(a1) + bb;
        }
    } else {
        // heads; 2-node chunks, sequential
        float dbi = __ldg(&db1[lane]), vbi = __ldg(&vb1[lane]);
        float w2d  = __ldg(&dw2[lane]);
        float w2v0 = __ldg(&vw2[lane * 2 + 0]);
        float w2v1 = __ldg(&vw2[lane * 2 + 1]);
#pragma unroll 1
        for (int c = 0; c < 2; c++) {
            u64 ad0 = 0, ad1 = 0, av0 = 0, av1 = 0;
            const float* ha = &hbuf[(nb + 2 * c) * 68];
            const float* hb = &hbuf[(nb + 2 * c + 1) * 68];
#pragma unroll 4
            for (int kp = 0; kp < 32; kp++) {
                u64 h0v = *(const u64*)(ha + 2 * kp);
                u64 h1v = *(const u64*)(hb + 2 * kp);
                u64 dwv = __ldg(&g_dw1p[kp * 32 + lane]);
                u64 vwv = __ldg(&g_vw1p[kp * 32 + lane]);
                ad0 = fma2(h0v, dwv, ad0); av0 = fma2(h0v, vwv, av0);
                ad1 = fma2(h1v, dwv, ad1); av1 = fma2(h1v, vwv, av1);
            }
#pragma unroll
            for (int s = 0; s < 2; s++) {
                float rd = fmaxf(pairsum(s ? ad1 : ad0) + dbi, 0.f);
                float rv = fmaxf(pairsum(s ? av1 : av0) + vbi, 0.f);
                float d  = rd * w2d;
                float v0 = rv * w2v0;
                float v1 = rv * w2v1;
#pragma unroll
                for (int o = 16; o; o >>= 1) {
                    d  += __shfl_xor_sync(FULL, d, o);
                    v0 += __shfl_xor_sync(FULL, v0, o);
                    v1 += __shfl_xor_sync(FULL, v1, o);
                }
                int idx = nb + 2 * c + s;
                int n = n0 + idx;
                if (lane == 0 && idx < rem) {
                    out[n] = d + __ldg(&db2[0]);
                    float2* vout = (float2*)(out + N_NODES);
                    vout[n] = make_float2(v0 + __ldg(&vb2[0]), v1 + __ldg(&vb2[1]));
                }
            }
        }
    }
}

// ---------------- launch ----------------
extern "C" void kernel_launch(void* const* d_in, const int* in_sizes, int n_in,
                              void* d_out, int out_size)
{
    const float* x       = (const float*)d_in[0];
    const int*   ei      = (const int*)  d_in[1];
    const float* ea      = (const float*)d_in[2];
    const float* enc_w   = (const float*)d_in[3];
    const float* enc_b   = (const float*)d_in[4];
    const float* enc_g   = (const float*)d_in[5];
    const float* enc_bt  = (const float*)d_in[6];
    const float* mlp_w1  = (const float*)d_in[7];   // [L, 67, 32]
    const float* mlp_b1  = (const float*)d_in[8];   // [L, 32]
    const float* mlp_w2  = (const float*)d_in[9];   // [L, 32, 64]
    const float* mlp_b2  = (const float*)d_in[10];  // [L, 64]
    const float* ln_g    = (const float*)d_in[11];  // [L, 64]
    const float* ln_b    = (const float*)d_in[12];  // [L, 64]
    const float* dw1     = (const float*)d_in[13];
    const float* db1     = (const float*)d_in[14];
    const float* dw2     = (const float*)d_in[15];
    const float* db2     = (const float*)d_in[16];
    const float* vw1     = (const float*)d_in[17];
    const float* vb1     = (const float*)d_in[18];
    const float* vw2     = (const float*)d_in[19];
    const float* vb2     = (const float*)d_in[20];
    float* out = (float*)d_out;

    const int TB = 256;
    const int enc_grid  = (N_NODES / 4 * 32 + TB - 1) / TB;   // 4 nodes/warp
    const int node_grid = (N_NODES + 31) / 32;                // 32 nodes/block
    const int edge_grid = (E_EDGES * 8 + TB - 1) / TB;        // 8 threads/edge

    pack_kernel<<<32, TB>>>(mlp_w1, mlp_w2, dw1, vw1);
    encoder_kernel<<<enc_grid, TB>>>(x, enc_w, enc_b, enc_g, enc_bt,
                                     mlp_w1, mlp_b1);

    for (int i = 0; i < NLAYERS; i++) {
        const float* w1 = mlp_w1 + (size_t)i * (HDIM + 3) * HH;
        const float* b2 = mlp_b2 + (size_t)i * HDIM;
        const float* lg = ln_g   + (size_t)i * HDIM;
        const float* lb = ln_b   + (size_t)i * HDIM;
        const float* b1n = mlp_b1 + (size_t)(i + 1) * HH;

        if (i == 0) edge_kernel<true ><<<edge_grid, TB>>>(ei, ea, w1);
        else        edge_kernel<false><<<edge_grid, TB>>>(ei, ea, w1);

        if (i + 1 < NLAYERS)
            node_agg_kernel<false><<<node_grid, TB>>>(i, b2, lg, lb, b1n,
                db1, dw2, db2, vb1, vw2, vb2, out);
        else
            node_agg_kernel<true ><<<node_grid, TB>>>(i, b2, lg, lb, nullptr,
                db1, dw2, db2, vb1, vw2, vb2, out);
    }
}

// round 11
// speedup vs baseline: 1.1559x; 1.1559x over previous
#include <cuda_runtime.h>
#include <cuda_bf16.h>

#define N_NODES 50000
#define E_EDGES 800000
#define IN_C    16
#define HDIM    64
#define HH      32
#define NLAYERS 3
#define FULL    0xffffffffu

// Scratch (device globals; float4 for 16B alignment)
__device__ float  g_h[N_NODES * HDIM];   // row-major [n][64], lane j holds (j, j+32)
__device__ float4 g_p4[N_NODES * 8];     // row-major [n][32]
__device__ float4 g_q4[N_NODES * 8];     // row-major [n][32]
__device__ float  g_cnt[N_NODES];

__device__ __forceinline__ void red_add_v4(float* ptr, float4 v) {
    asm volatile("red.global.add.v4.f32 [%0], {%1,%2,%3,%4};"
                 :: "l"(ptr), "f"(v.x), "f"(v.y), "f"(v.z), "f"(v.w) : "memory");
}

// ---------------- encoder: h + p0 + zero q/cnt ----------------
__global__ __launch_bounds__(256) void encoder_kernel(
    const float* __restrict__ x,  const float* __restrict__ w,
    const float* __restrict__ b,  const float* __restrict__ g,
    const float* __restrict__ beta,
    const float* __restrict__ w1, const float* __restrict__ b1)
{
    int warp = (blockIdx.x * blockDim.x + threadIdx.x) >> 5;
    int lane = threadIdx.x & 31;
    int n0   = warp * 4;
    if (n0 >= N_NODES) return;

    float* g_p = (float*)g_p4;
    float* g_q = (float*)g_q4;

    float xv[4], a0[4], a1[4];
#pragma unroll
    for (int i = 0; i < 4; i++) {
        xv[i] = (lane < IN_C) ? x[(n0 + i) * IN_C + lane] : 0.0f;
        a0[i] = __ldg(&b[lane]);
        a1[i] = __ldg(&b[lane + 32]);
    }
#pragma unroll
    for (int k = 0; k < IN_C; k++) {
        float w0 = __ldg(&w[k * HDIM + lane]);
        float w1v = __ldg(&w[k * HDIM + 32 + lane]);
#pragma unroll
        for (int i = 0; i < 4; i++) {
            float xk = __shfl_sync(FULL, xv[i], k);
            a0[i] = fmaf(xk, w0, a0[i]);
            a1[i] = fmaf(xk, w1v, a1[i]);
        }
    }
    float gl = __ldg(&g[lane]), gh = __ldg(&g[lane + 32]);
    float bl = __ldg(&beta[lane]), bh = __ldg(&beta[lane + 32]);
    float h0[4], h1[4];
#pragma unroll
    for (int i = 0; i < 4; i++) {
        float s1 = a0[i] + a1[i], s2 = a0[i] * a0[i] + a1[i] * a1[i];
#pragma unroll
        for (int o = 16; o; o >>= 1) {
            s1 += __shfl_xor_sync(FULL, s1, o);
            s2 += __shfl_xor_sync(FULL, s2, o);
        }
        float mu  = s1 * (1.0f / 64.0f);
        float var = s2 * (1.0f / 64.0f) - mu * mu;
        float rs  = rsqrtf(var + 1e-5f);
        h0[i] = fmaxf(fmaf((a0[i] - mu) * rs, gl, bl), 0.0f);
        h1[i] = fmaxf(fmaf((a1[i] - mu) * rs, gh, bh), 0.0f);
        g_h[(n0 + i) * HDIM + lane]      = h0[i];
        g_h[(n0 + i) * HDIM + 32 + lane] = h1[i];
    }
    float acc[4];
#pragma unroll
    for (int i = 0; i < 4; i++) acc[i] = __ldg(&b1[lane]);
#pragma unroll
    for (int k = 0; k < 32; k++) {
        float wk = __ldg(&w1[k * HH + lane]);
#pragma unroll
        for (int i = 0; i < 4; i++)
            acc[i] = fmaf(__shfl_sync(FULL, h0[i], k), wk, acc[i]);
    }
#pragma unroll
    for (int k = 0; k < 32; k++) {
        float wk = __ldg(&w1[(32 + k) * HH + lane]);
#pragma unroll
        for (int i = 0; i < 4; i++)
            acc[i] = fmaf(__shfl_sync(FULL, h1[i], k), wk, acc[i]);
    }
#pragma unroll
    for (int i = 0; i < 4; i++) {
        g_p[(n0 + i) * HH + lane] = acc[i];
        g_q[(n0 + i) * HH + lane] = 0.0f;
    }
    if (lane < 4) g_cnt[n0 + lane] = 0.0f;
}

// ------- edge kernel: 4 threads/edge, 2 quads each; COUNT folds in-degree -------
template<bool COUNT>
__global__ __launch_bounds__(256) void edge_kernel(
    const int* __restrict__ ei, const float* __restrict__ ea,
    const float* __restrict__ w1)
{
    int idx = blockIdx.x * blockDim.x + threadIdx.x;
    int e = idx >> 2, q0 = idx & 3;      // quads q0 and q0+4
    if (e >= E_EDGES) return;

    int src = __ldg(&ei[e]);
    int dst = __ldg(&ei[E_EDGES + e]);
    float e0 = __ldg(&ea[e * 3 + 0]);
    float e1 = __ldg(&ea[e * 3 + 1]);
    float e2 = __ldg(&ea[e * 3 + 2]);

    const float4* W = (const float4*)(w1 + 64 * HH);

#pragma unroll
    for (int s = 0; s < 2; s++) {
        int quad = q0 + 4 * s;
        float4 p  = __ldg(&g_p4[src * 8 + quad]);
        float4 wa = __ldg(&W[quad]);
        float4 wb = __ldg(&W[8 + quad]);
        float4 wc = __ldg(&W[16 + quad]);
        float4 v;
        v.x = fmaxf(fmaf(e2, wc.x, fmaf(e1, wb.x, fmaf(e0, wa.x, p.x))), 0.0f);
        v.y = fmaxf(fmaf(e2, wc.y, fmaf(e1, wb.y, fmaf(e0, wa.y, p.y))), 0.0f);
        v.z = fmaxf(fmaf(e2, wc.z, fmaf(e1, wb.z, fmaf(e0, wa.z, p.z))), 0.0f);
        v.w = fmaxf(fmaf(e2, wc.w, fmaf(e1, wb.w, fmaf(e0, wa.w, p.w))), 0.0f);
        red_add_v4((float*)&g_q4[dst * 8 + quad], v);
    }
    if (COUNT && q0 == 0) atomicAdd(&g_cnt[dst], 1.0f);
}

// ---- stage-2 + mean + residual + LN; transposed-smem broadcast; LAST fuses heads ----
template<bool LAST>
__global__ __launch_bounds__(256) void node_agg_kernel(
    const float* __restrict__ w2,  const float* __restrict__ b2,
    const float* __restrict__ g,   const float* __restrict__ beta,
    const float* __restrict__ w1n, const float* __restrict__ b1n,
    const float* __restrict__ dw1, const float* __restrict__ db1,
    const float* __restrict__ dw2, const float* __restrict__ db2,
    const float* __restrict__ vw1, const float* __restrict__ vb1,
    const float* __restrict__ vw2, const float* __restrict__ vb2,
    float* __restrict__ out)
{
    __shared__ float sbuf[64 * 36];   // [k][node], stride 36
    int t = threadIdx.x, w = t >> 5, lane = t & 31;
    int n0 = blockIdx.x * 32;
    int rem = N_NODES - n0; if (rem > 32) rem = 32;

    // stage q transposed; zero q behind us
    {
        int nl = t >> 3, k0 = (t & 7) << 2;
        float4 v = make_float4(0.f, 0.f, 0.f, 0.f);
        float4* qp = (float4*)g_q4 + (size_t)n0 * 8 + t;
        if (nl < rem) { v = *qp; *qp = make_float4(0.f, 0.f, 0.f, 0.f); }
        sbuf[(k0 + 0) * 36 + nl] = v.x;
        sbuf[(k0 + 1) * 36 + nl] = v.y;
        sbuf[(k0 + 2) * 36 + nl] = v.z;
        sbuf[(k0 + 3) * 36 + nl] = v.w;
    }
    __syncthreads();

    int nb = w * 4;

    float o0[4] = {0, 0, 0, 0}, o1[4] = {0, 0, 0, 0};
#pragma unroll
    for (int k = 0; k < 32; k++) {
        float4 qv = *(const float4*)&sbuf[k * 36 + nb];
        float wlo = __ldg(&w2[k * HDIM + lane]);
        float whi = __ldg(&w2[k * HDIM + 32 + lane]);
        o0[0] = fmaf(qv.x, wlo, o0[0]); o1[0] = fmaf(qv.x, whi, o1[0]);
        o0[1] = fmaf(qv.y, wlo, o0[1]); o1[1] = fmaf(qv.y, whi, o1[1]);
        o0[2] = fmaf(qv.z, wlo, o0[2]); o1[2] = fmaf(qv.z, whi, o1[2]);
        o0[3] = fmaf(qv.w, wlo, o0[3]); o1[3] = fmaf(qv.w, whi, o1[3]);
    }
    float b2l = __ldg(&b2[lane]),  b2h = __ldg(&b2[32 + lane]);
    float gl  = __ldg(&g[lane]),   gh  = __ldg(&g[lane + 32]);
    float bl  = __ldg(&beta[lane]), bh = __ldg(&beta[lane + 32]);

    float h0[4], h1[4];
#pragma unroll
    for (int i = 0; i < 4; i++) {
        int n = n0 + nb + i;
        bool act = (nb + i) < rem;
        float c   = act ? g_cnt[n] : 0.f;
        float inv = (c > 0.f) ? (1.f / c) : 0.f;
        float has = (c > 0.f) ? 1.f : 0.f;
        float hh0 = act ? g_h[(size_t)n * HDIM + lane] : 0.f;
        float hh1 = act ? g_h[(size_t)n * HDIM + 32 + lane] : 0.f;
        float a0 = hh0 + o0[i] * inv + has * b2l;
        float a1 = hh1 + o1[i] * inv + has * b2h;
        float s1 = a0 + a1, s2 = a0 * a0 + a1 * a1;
#pragma unroll
        for (int o = 16; o; o >>= 1) {
            s1 += __shfl_xor_sync(FULL, s1, o);
            s2 += __shfl_xor_sync(FULL, s2, o);
        }
        float mu  = s1 * (1.f / 64.f);
        float var = s2 * (1.f / 64.f) - mu * mu;
        float rs  = rsqrtf(var + 1e-5f);
        h0[i] = fmaf((a0 - mu) * rs, gl, bl);
        h1[i] = fmaf((a1 - mu) * rs, gh, bh);
        if (!LAST && act) {
            g_h[(size_t)n * HDIM + lane]      = h0[i];
            g_h[(size_t)n * HDIM + 32 + lane] = h1[i];
        }
    }
    __syncthreads();

#pragma unroll
    for (int i = 0; i < 4; i++) {
        sbuf[lane * 36 + nb + i]        = h0[i];
        sbuf[(lane + 32) * 36 + nb + i] = h1[i];
    }
    __syncthreads();

    if (!LAST) {
        float pacc[4];
        float bb = __ldg(&b1n[lane]);
#pragma unroll
        for (int i = 0; i < 4; i++) pacc[i] = bb;
#pragma unroll
        for (int k = 0; k < 64; k++) {
            float4 hv = *(const float4*)&sbuf[k * 36 + nb];
            float wk = __ldg(&w1n[k * HH + lane]);
            pacc[0] = fmaf(hv.x, wk, pacc[0]);
            pacc[1] = fmaf(hv.y, wk, pacc[1]);
            pacc[2] = fmaf(hv.z, wk, pacc[2]);
            pacc[3] = fmaf(hv.w, wk, pacc[3]);
        }
        float* gp = (float*)g_p4;
#pragma unroll
        for (int i = 0; i < 4; i++)
            if ((nb + i) < rem) gp[(size_t)(n0 + nb + i) * HH + lane] = pacc[i];
    } else {
        float da[4], va[4];
        float dbi = __ldg(&db1[lane]), vbi = __ldg(&vb1[lane]);
#pragma unroll
        for (int i = 0; i < 4; i++) { da[i] = dbi; va[i] = vbi; }
#pragma unroll
        for (int k = 0; k < 64; k++) {
            float4 hv = *(const float4*)&sbuf[k * 36 + nb];
            float dwk = __ldg(&dw1[k * HH + lane]);
            float vwk = __ldg(&vw1[k * HH + lane]);
            da[0] = fmaf(hv.x, dwk, da[0]); va[0] = fmaf(hv.x, vwk, va[0]);
            da[1] = fmaf(hv.y, dwk, da[1]); va[1] = fmaf(hv.y, vwk, va[1]);
            da[2] = fmaf(hv.z, dwk, da[2]); va[2] = fmaf(hv.z, vwk, va[2]);
            da[3] = fmaf(hv.w, dwk, da[3]); va[3] = fmaf(hv.w, vwk, va[3]);
        }
        float w2d  = __ldg(&dw2[lane]);
        float w2v0 = __ldg(&vw2[lane * 2 + 0]);
        float w2v1 = __ldg(&vw2[lane * 2 + 1]);
#pragma unroll
        for (int i = 0; i < 4; i++) {
            float rd = fmaxf(da[i], 0.f), rv = fmaxf(va[i], 0.f);
            float d  = rd * w2d;
            float v0 = rv * w2v0;
            float v1 = rv * w2v1;
#pragma unroll
            for (int o = 16; o; o >>= 1) {
                d  += __shfl_xor_sync(FULL, d, o);
                v0 += __shfl_xor_sync(FULL, v0, o);
                v1 += __shfl_xor_sync(FULL, v1, o);
            }
            int n = n0 + nb + i;
            if (lane == 0 && (nb + i) < rem) {
                out[n] = d + __ldg(&db2[0]);
                float2* vout = (float2*)(out + N_NODES);
                vout[n] = make_float2(v0 + __ldg(&vb2[0]), v1 + __ldg(&vb2[1]));
            }
        }
    }
}

// ---------------- launch ----------------
extern "C" void kernel_launch(void* const* d_in, const int* in_sizes, int n_in,
                              void* d_out, int out_size)
{
    const float* x       = (const float*)d_in[0];
    const int*   ei      = (const int*)  d_in[1];
    const float* ea      = (const float*)d_in[2];
    const float* enc_w   = (const float*)d_in[3];
    const float* enc_b   = (const float*)d_in[4];
    const float* enc_g   = (const float*)d_in[5];
    const float* enc_bt  = (const float*)d_in[6];
    const float* mlp_w1  = (const float*)d_in[7];   // [L, 67, 32]
    const float* mlp_b1  = (const float*)d_in[8];   // [L, 32]
    const float* mlp_w2  = (const float*)d_in[9];   // [L, 32, 64]
    const float* mlp_b2  = (const float*)d_in[10];  // [L, 64]
    const float* ln_g    = (const float*)d_in[11];  // [L, 64]
    const float* ln_b    = (const float*)d_in[12];  // [L, 64]
    const float* dw1     = (const float*)d_in[13];
    const float* db1     = (const float*)d_in[14];
    const float* dw2     = (const float*)d_in[15];
    const float* db2     = (const float*)d_in[16];
    const float* vw1     = (const float*)d_in[17];
    const float* vb1     = (const float*)d_in[18];
    const float* vw2     = (const float*)d_in[19];
    const float* vb2     = (const float*)d_in[20];
    float* out = (float*)d_out;

    const int TB = 256;
    const int enc_grid  = (N_NODES / 4 * 32 + TB - 1) / TB;   // 4 nodes/warp
    const int node_grid = (N_NODES + 31) / 32;                // 32 nodes/block
    const int edge_grid = (E_EDGES * 4 + TB - 1) / TB;        // 4 threads/edge

    encoder_kernel<<<enc_grid, TB>>>(x, enc_w, enc_b, enc_g, enc_bt,
                                     mlp_w1, mlp_b1);

    for (int i = 0; i < NLAYERS; i++) {
        const float* w1 = mlp_w1 + (size_t)i * (HDIM + 3) * HH;
        const float* w2 = mlp_w2 + (size_t)i * HH * HDIM;
        const float* b2 = mlp_b2 + (size_t)i * HDIM;
        const float* lg = ln_g   + (size_t)i * HDIM;
        const float* lb = ln_b   + (size_t)i * HDIM;
        const float* w1n = mlp_w1 + (size_t)(i + 1) * (HDIM + 3) * HH;
        const float* b1n = mlp_b1 + (size_t)(i + 1) * HH;

        if (i == 0) edge_kernel<true ><<<edge_grid, TB>>>(ei, ea, w1);
        else        edge_kernel<false><<<edge_grid, TB>>>(ei, ea, w1);

        if (i + 1 < NLAYERS)
            node_agg_kernel<false><<<node_grid, TB>>>(w2, b2, lg, lb, w1n, b1n,
                dw1, db1, dw2, db2, vw1, vb1, vw2, vb2, out);
        else
            node_agg_kernel<true ><<<node_grid, TB>>>(w2, b2, lg, lb, nullptr, nullptr,
                dw1, db1, dw2, db2, vw1, vb1, vw2, vb2, out);
    }
}

// round 12
// speedup vs baseline: 1.2811x; 1.1084x over previous
#include <cuda_runtime.h>
#include <cuda_fp16.h>

#define N_NODES 50000
#define E_EDGES 800000
#define IN_C    16
#define HDIM    64
#define HH      32
#define NLAYERS 3
#define FULL    0xffffffffu

// Scratch (device globals)
__device__ float  g_h[N_NODES * HDIM];   // row-major [n][64], lane j holds (j, j+32)
__device__ float4 g_p4[N_NODES * 8];     // row-major [n][32] fp32
__device__ uint4  g_qh4[N_NODES * 4];    // row-major [n][32] fp16 (64B/node)
__device__ float  g_cnt[N_NODES];

__device__ __forceinline__ unsigned pack_half2(float lo, float hi) {
    __half2 h = __floats2half2_rn(lo, hi);
    return *reinterpret_cast<unsigned*>(&h);
}
__device__ __forceinline__ void red_add_v4_f16x2(__half* ptr, unsigned a, unsigned b,
                                                 unsigned c, unsigned d) {
    asm volatile("red.global.add.noftz.v4.f16x2 [%0], {%1,%2,%3,%4};"
                 :: "l"(ptr), "r"(a), "r"(b), "r"(c), "r"(d) : "memory");
}

// ---------------- encoder: h + p0 + zero q/cnt ----------------
__global__ __launch_bounds__(256) void encoder_kernel(
    const float* __restrict__ x,  const float* __restrict__ w,
    const float* __restrict__ b,  const float* __restrict__ g,
    const float* __restrict__ beta,
    const float* __restrict__ w1, const float* __restrict__ b1)
{
    int warp = (blockIdx.x * blockDim.x + threadIdx.x) >> 5;
    int lane = threadIdx.x & 31;
    int n0   = warp * 4;
    if (n0 >= N_NODES) return;

    float* g_p = (float*)g_p4;

    float xv[4], a0[4], a1[4];
#pragma unroll
    for (int i = 0; i < 4; i++) {
        xv[i] = (lane < IN_C) ? x[(n0 + i) * IN_C + lane] : 0.0f;
        a0[i] = __ldg(&b[lane]);
        a1[i] = __ldg(&b[lane + 32]);
    }
#pragma unroll
    for (int k = 0; k < IN_C; k++) {
        float w0 = __ldg(&w[k * HDIM + lane]);
        float w1v = __ldg(&w[k * HDIM + 32 + lane]);
#pragma unroll
        for (int i = 0; i < 4; i++) {
            float xk = __shfl_sync(FULL, xv[i], k);
            a0[i] = fmaf(xk, w0, a0[i]);
            a1[i] = fmaf(xk, w1v, a1[i]);
        }
    }
    float gl = __ldg(&g[lane]), gh = __ldg(&g[lane + 32]);
    float bl = __ldg(&beta[lane]), bh = __ldg(&beta[lane + 32]);
    float h0[4], h1[4];
#pragma unroll
    for (int i = 0; i < 4; i++) {
        float s1 = a0[i] + a1[i], s2 = a0[i] * a0[i] + a1[i] * a1[i];
#pragma unroll
        for (int o = 16; o; o >>= 1) {
            s1 += __shfl_xor_sync(FULL, s1, o);
            s2 += __shfl_xor_sync(FULL, s2, o);
        }
        float mu  = s1 * (1.0f / 64.0f);
        float var = s2 * (1.0f / 64.0f) - mu * mu;
        float rs  = rsqrtf(var + 1e-5f);
        h0[i] = fmaxf(fmaf((a0[i] - mu) * rs, gl, bl), 0.0f);
        h1[i] = fmaxf(fmaf((a1[i] - mu) * rs, gh, bh), 0.0f);
        g_h[(n0 + i) * HDIM + lane]      = h0[i];
        g_h[(n0 + i) * HDIM + 32 + lane] = h1[i];
    }
    float acc[4];
#pragma unroll
    for (int i = 0; i < 4; i++) acc[i] = __ldg(&b1[lane]);
#pragma unroll
    for (int k = 0; k < 32; k++) {
        float wk = __ldg(&w1[k * HH + lane]);
#pragma unroll
        for (int i = 0; i < 4; i++)
            acc[i] = fmaf(__shfl_sync(FULL, h0[i], k), wk, acc[i]);
    }
#pragma unroll
    for (int k = 0; k < 32; k++) {
        float wk = __ldg(&w1[(32 + k) * HH + lane]);
#pragma unroll
        for (int i = 0; i < 4; i++)
            acc[i] = fmaf(__shfl_sync(FULL, h1[i], k), wk, acc[i]);
    }
#pragma unroll
    for (int i = 0; i < 4; i++)
        g_p[(n0 + i) * HH + lane] = acc[i];

    // zero q (fp16, 4 nodes × 64B = 16 uint4) and cnt
    if (lane < 16) g_qh4[n0 * 4 + lane] = make_uint4(0, 0, 0, 0);
    if (lane < 4)  g_cnt[n0 + lane] = 0.0f;
}

// ------- edge kernel: 4 threads/edge, fp16 v4.f16x2 RED (4 lanes/edge) -------
template<bool COUNT>
__global__ __launch_bounds__(256) void edge_kernel(
    const int* __restrict__ ei, const float* __restrict__ ea,
    const float* __restrict__ w1)
{
    int idx = blockIdx.x * blockDim.x + threadIdx.x;
    int e = idx >> 2, q0 = idx & 3;      // this thread covers floats [8*q0, 8*q0+8)
    if (e >= E_EDGES) return;

    int src = __ldg(&ei[e]);
    int dst = __ldg(&ei[E_EDGES + e]);
    float e0 = __ldg(&ea[e * 3 + 0]);
    float e1 = __ldg(&ea[e * 3 + 1]);
    float e2 = __ldg(&ea[e * 3 + 2]);

    const float4* W = (const float4*)(w1 + 64 * HH);
    float v[8];
#pragma unroll
    for (int s = 0; s < 2; s++) {
        int quad = 2 * q0 + s;
        float4 p  = __ldg(&g_p4[src * 8 + quad]);
        float4 wa = __ldg(&W[quad]);
        float4 wb = __ldg(&W[8 + quad]);
        float4 wc = __ldg(&W[16 + quad]);
        v[4 * s + 0] = fmaxf(fmaf(e2, wc.x, fmaf(e1, wb.x, fmaf(e0, wa.x, p.x))), 0.0f);
        v[4 * s + 1] = fmaxf(fmaf(e2, wc.y, fmaf(e1, wb.y, fmaf(e0, wa.y, p.y))), 0.0f);
        v[4 * s + 2] = fmaxf(fmaf(e2, wc.z, fmaf(e1, wb.z, fmaf(e0, wa.z, p.z))), 0.0f);
        v[4 * s + 3] = fmaxf(fmaf(e2, wc.w, fmaf(e1, wb.w, fmaf(e0, wa.w, p.w))), 0.0f);
    }
    unsigned u0 = pack_half2(v[0], v[1]);
    unsigned u1 = pack_half2(v[2], v[3]);
    unsigned u2 = pack_half2(v[4], v[5]);
    unsigned u3 = pack_half2(v[6], v[7]);
    __half* qp = (__half*)g_qh4 + (size_t)dst * 32 + 8 * q0;
    red_add_v4_f16x2(qp, u0, u1, u2, u3);

    if (COUNT && q0 == 0) atomicAdd(&g_cnt[dst], 1.0f);
}

// ---- stage-2 + mean + residual + LN; transposed-smem broadcast; LAST fuses heads ----
template<bool LAST>
__global__ __launch_bounds__(256) void node_agg_kernel(
    const float* __restrict__ w2,  const float* __restrict__ b2,
    const float* __restrict__ g,   const float* __restrict__ beta,
    const float* __restrict__ w1n, const float* __restrict__ b1n,
    const float* __restrict__ dw1, const float* __restrict__ db1,
    const float* __restrict__ dw2, const float* __restrict__ db2,
    const float* __restrict__ vw1, const float* __restrict__ vb1,
    const float* __restrict__ vw2, const float* __restrict__ vb2,
    float* __restrict__ out)
{
    __shared__ float sbuf[64 * 36];   // [k][node], stride 36
    int t = threadIdx.x, w = t >> 5, lane = t & 31;
    int n0 = blockIdx.x * 32;
    int rem = N_NODES - n0; if (rem > 32) rem = 32;

    // stage q (fp16 -> fp32) transposed; zero q behind us
    {
        int nl = t >> 3, k0 = (t & 7) << 2;   // 4 halfs (8B) per thread
        float2 f01 = make_float2(0.f, 0.f), f23 = make_float2(0.f, 0.f);
        __half* qp = (__half*)g_qh4 + (size_t)(n0 + nl) * 32 + k0;
        if (nl < rem) {
            uint2 raw = *(uint2*)qp;
            f01 = __half22float2(*reinterpret_cast<__half2*>(&raw.x));
            f23 = __half22float2(*reinterpret_cast<__half2*>(&raw.y));
            *(uint2*)qp = make_uint2(0, 0);
        }
        sbuf[(k0 + 0) * 36 + nl] = f01.x;
        sbuf[(k0 + 1) * 36 + nl] = f01.y;
        sbuf[(k0 + 2) * 36 + nl] = f23.x;
        sbuf[(k0 + 3) * 36 + nl] = f23.y;
    }
    __syncthreads();

    int nb = w * 4;

    float o0[4] = {0, 0, 0, 0}, o1[4] = {0, 0, 0, 0};
#pragma unroll
    for (int k = 0; k < 32; k++) {
        float4 qv = *(const float4*)&sbuf[k * 36 + nb];
        float wlo = __ldg(&w2[k * HDIM + lane]);
        float whi = __ldg(&w2[k * HDIM + 32 + lane]);
        o0[0] = fmaf(qv.x, wlo, o0[0]); o1[0] = fmaf(qv.x, whi, o1[0]);
        o0[1] = fmaf(qv.y, wlo, o0[1]); o1[1] = fmaf(qv.y, whi, o1[1]);
        o0[2] = fmaf(qv.z, wlo, o0[2]); o1[2] = fmaf(qv.z, whi, o1[2]);
        o0[3] = fmaf(qv.w, wlo, o0[3]); o1[3] = fmaf(qv.w, whi, o1[3]);
    }
    float b2l = __ldg(&b2[lane]),  b2h = __ldg(&b2[32 + lane]);
    float gl  = __ldg(&g[lane]),   gh  = __ldg(&g[lane + 32]);
    float bl  = __ldg(&beta[lane]), bh = __ldg(&beta[lane + 32]);

    float h0[4], h1[4];
#pragma unroll
    for (int i = 0; i < 4; i++) {
        int n = n0 + nb + i;
        bool act = (nb + i) < rem;
        float c   = act ? g_cnt[n] : 0.f;
        float inv = (c > 0.f) ? (1.f / c) : 0.f;
        float has = (c > 0.f) ? 1.f : 0.f;
        float hh0 = act ? g_h[(size_t)n * HDIM + lane] : 0.f;
        float hh1 = act ? g_h[(size_t)n * HDIM + 32 + lane] : 0.f;
        float a0 = hh0 + o0[i] * inv + has * b2l;
        float a1 = hh1 + o1[i] * inv + has * b2h;
        float s1 = a0 + a1, s2 = a0 * a0 + a1 * a1;
#pragma unroll
        for (int o = 16; o; o >>= 1) {
            s1 += __shfl_xor_sync(FULL, s1, o);
            s2 += __shfl_xor_sync(FULL, s2, o);
        }
        float mu  = s1 * (1.f / 64.f);
        float var = s2 * (1.f / 64.f) - mu * mu;
        float rs  = rsqrtf(var + 1e-5f);
        h0[i] = fmaf((a0 - mu) * rs, gl, bl);
        h1[i] = fmaf((a1 - mu) * rs, gh, bh);
        if (!LAST && act) {
            g_h[(size_t)n * HDIM + lane]      = h0[i];
            g_h[(size_t)n * HDIM + 32 + lane] = h1[i];
        }
    }
    __syncthreads();

#pragma unroll
    for (int i = 0; i < 4; i++) {
        sbuf[lane * 36 + nb + i]        = h0[i];
        sbuf[(lane + 32) * 36 + nb + i] = h1[i];
    }
    __syncthreads();

    if (!LAST) {
        float pacc[4];
        float bb = __ldg(&b1n[lane]);
#pragma unroll
        for (int i = 0; i < 4; i++) pacc[i] = bb;
#pragma unroll
        for (int k = 0; k < 64; k++) {
            float4 hv = *(const float4*)&sbuf[k * 36 + nb];
            float wk = __ldg(&w1n[k * HH + lane]);
            pacc[0] = fmaf(hv.x, wk, pacc[0]);
            pacc[1] = fmaf(hv.y, wk, pacc[1]);
            pacc[2] = fmaf(hv.z, wk, pacc[2]);
            pacc[3] = fmaf(hv.w, wk, pacc[3]);
        }
        float* gp = (float*)g_p4;
#pragma unroll
        for (int i = 0; i < 4; i++)
            if ((nb + i) < rem) gp[(size_t)(n0 + nb + i) * HH + lane] = pacc[i];
    } else {
        float da[4], va[4];
        float dbi = __ldg(&db1[lane]), vbi = __ldg(&vb1[lane]);
#pragma unroll
        for (int i = 0; i < 4; i++) { da[i] = dbi; va[i] = vbi; }
#pragma unroll
        for (int k = 0; k < 64; k++) {
            float4 hv = *(const float4*)&sbuf[k * 36 + nb];
            float dwk = __ldg(&dw1[k * HH + lane]);
            float vwk = __ldg(&vw1[k * HH + lane]);
            da[0] = fmaf(hv.x, dwk, da[0]); va[0] = fmaf(hv.x, vwk, va[0]);
            da[1] = fmaf(hv.y, dwk, da[1]); va[1] = fmaf(hv.y, vwk, va[1]);
            da[2] = fmaf(hv.z, dwk, da[2]); va[2] = fmaf(hv.z, vwk, va[2]);
            da[3] = fmaf(hv.w, dwk, da[3]); va[3] = fmaf(hv.w, vwk, va[3]);
        }
        float w2d  = __ldg(&dw2[lane]);
        float w2v0 = __ldg(&vw2[lane * 2 + 0]);
        float w2v1 = __ldg(&vw2[lane * 2 + 1]);
#pragma unroll
        for (int i = 0; i < 4; i++) {
            float rd = fmaxf(da[i], 0.f), rv = fmaxf(va[i], 0.f);
            float d  = rd * w2d;
            float v0 = rv * w2v0;
            float v1 = rv * w2v1;
#pragma unroll
            for (int o = 16; o; o >>= 1) {
                d  += __shfl_xor_sync(FULL, d, o);
                v0 += __shfl_xor_sync(FULL, v0, o);
                v1 += __shfl_xor_sync(FULL, v1, o);
            }
            int n = n0 + nb + i;
            if (lane == 0 && (nb + i) < rem) {
                out[n] = d + __ldg(&db2[0]);
                float2* vout = (float2*)(out + N_NODES);
                vout[n] = make_float2(v0 + __ldg(&vb2[0]), v1 + __ldg(&vb2[1]));
            }
        }
    }
}

// ---------------- launch ----------------
extern "C" void kernel_launch(void* const* d_in, const int* in_sizes, int n_in,
                              void* d_out, int out_size)
{
    const float* x       = (const float*)d_in[0];
    const int*   ei      = (const int*)  d_in[1];
    const float* ea      = (const float*)d_in[2];
    const float* enc_w   = (const float*)d_in[3];
    const float* enc_b   = (const float*)d_in[4];
    const float* enc_g   = (const float*)d_in[5];
    const float* enc_bt  = (const float*)d_in[6];
    const float* mlp_w1  = (const float*)d_in[7];   // [L, 67, 32]
    const float* mlp_b1  = (const float*)d_in[8];   // [L, 32]
    const float* mlp_w2  = (const float*)d_in[9];   // [L, 32, 64]
    const float* mlp_b2  = (const float*)d_in[10];  // [L, 64]
    const float* ln_g    = (const float*)d_in[11];  // [L, 64]
    const float* ln_b    = (const float*)d_in[12];  // [L, 64]
    const float* dw1     = (const float*)d_in[13];
    const float* db1     = (const float*)d_in[14];
    const float* dw2     = (const float*)d_in[15];
    const float* db2     = (const float*)d_in[16];
    const float* vw1     = (const float*)d_in[17];
    const float* vb1     = (const float*)d_in[18];
    const float* vw2     = (const float*)d_in[19];
    const float* vb2     = (const float*)d_in[20];
    float* out = (float*)d_out;

    const int TB = 256;
    const int enc_grid  = (N_NODES / 4 * 32 + TB - 1) / TB;   // 4 nodes/warp
    const int node_grid = (N_NODES + 31) / 32;                // 32 nodes/block
    const int edge_grid = (E_EDGES * 4 + TB - 1) / TB;        // 4 threads/edge

    encoder_kernel<<<enc_grid, TB>>>(x, enc_w, enc_b, enc_g, enc_bt,
                                     mlp_w1, mlp_b1);

    for (int i = 0; i < NLAYERS; i++) {
        const float* w1 = mlp_w1 + (size_t)i * (HDIM + 3) * HH;
        const float* w2 = mlp_w2 + (size_t)i * HH * HDIM;
        const float* b2 = mlp_b2 + (size_t)i * HDIM;
        const float* lg = ln_g   + (size_t)i * HDIM;
        const float* lb = ln_b   + (size_t)i * HDIM;
        const float* w1n = mlp_w1 + (size_t)(i + 1) * (HDIM + 3) * HH;
        const float* b1n = mlp_b1 + (size_t)(i + 1) * HH;

        if (i == 0) edge_kernel<true ><<<edge_grid, TB>>>(ei, ea, w1);
        else        edge_kernel<false><<<edge_grid, TB>>>(ei, ea, w1);

        if (i + 1 < NLAYERS)
            node_agg_kernel<false><<<node_grid, TB>>>(w2, b2, lg, lb, w1n, b1n,
                dw1, db1, dw2, db2, vw1, vb1, vw2, vb2, out);
        else
            node_agg_kernel<true ><<<node_grid, TB>>>(w2, b2, lg, lb, nullptr, nullptr,
                dw1, db1, dw2, db2, vw1, vb1, vw2, vb2, out);
    }
}

// round 13
// speedup vs baseline: 1.3570x; 1.0592x over previous
#include <cuda_runtime.h>
#include <cuda_fp16.h>

#define N_NODES 50000
#define E_EDGES 800000
#define IN_C    16
#define HDIM    64
#define HH      32
#define NLAYERS 3
#define FULL    0xffffffffu

// Scratch (device globals)
__device__ float  g_h[N_NODES * HDIM];   // row-major [n][64], lane j holds (j, j+32)
__device__ uint4  g_ph4[N_NODES * 4];    // row-major [n][32] fp16 p (64B/node)
__device__ uint4  g_qh4[N_NODES * 4];    // row-major [n][32] fp16 q (64B/node)
__device__ float  g_cnt[N_NODES];

__device__ __forceinline__ unsigned pack_half2(float lo, float hi) {
    __half2 h = __floats2half2_rn(lo, hi);
    return *reinterpret_cast<unsigned*>(&h);
}
__device__ __forceinline__ float2 unpack_half2(unsigned u) {
    return __half22float2(*reinterpret_cast<__half2*>(&u));
}
__device__ __forceinline__ void red_add_v4_f16x2(__half* ptr, unsigned a, unsigned b,
                                                 unsigned c, unsigned d) {
    asm volatile("red.global.add.noftz.v4.f16x2 [%0], {%1,%2,%3,%4};"
                 :: "l"(ptr), "r"(a), "r"(b), "r"(c), "r"(d) : "memory");
}

// ---------------- encoder: h + p0(fp16) + zero q/cnt ----------------
__global__ __launch_bounds__(256) void encoder_kernel(
    const float* __restrict__ x,  const float* __restrict__ w,
    const float* __restrict__ b,  const float* __restrict__ g,
    const float* __restrict__ beta,
    const float* __restrict__ w1, const float* __restrict__ b1)
{
    int warp = (blockIdx.x * blockDim.x + threadIdx.x) >> 5;
    int lane = threadIdx.x & 31;
    int n0   = warp * 4;
    if (n0 >= N_NODES) return;

    float xv[4], a0[4], a1[4];
#pragma unroll
    for (int i = 0; i < 4; i++) {
        xv[i] = (lane < IN_C) ? x[(n0 + i) * IN_C + lane] : 0.0f;
        a0[i] = __ldg(&b[lane]);
        a1[i] = __ldg(&b[lane + 32]);
    }
#pragma unroll
    for (int k = 0; k < IN_C; k++) {
        float w0 = __ldg(&w[k * HDIM + lane]);
        float w1v = __ldg(&w[k * HDIM + 32 + lane]);
#pragma unroll
        for (int i = 0; i < 4; i++) {
            float xk = __shfl_sync(FULL, xv[i], k);
            a0[i] = fmaf(xk, w0, a0[i]);
            a1[i] = fmaf(xk, w1v, a1[i]);
        }
    }
    float gl = __ldg(&g[lane]), gh = __ldg(&g[lane + 32]);
    float bl = __ldg(&beta[lane]), bh = __ldg(&beta[lane + 32]);
    float h0[4], h1[4];
#pragma unroll
    for (int i = 0; i < 4; i++) {
        float s1 = a0[i] + a1[i], s2 = a0[i] * a0[i] + a1[i] * a1[i];
#pragma unroll
        for (int o = 16; o; o >>= 1) {
            s1 += __shfl_xor_sync(FULL, s1, o);
            s2 += __shfl_xor_sync(FULL, s2, o);
        }
        float mu  = s1 * (1.0f / 64.0f);
        float var = s2 * (1.0f / 64.0f) - mu * mu;
        float rs  = rsqrtf(var + 1e-5f);
        h0[i] = fmaxf(fmaf((a0[i] - mu) * rs, gl, bl), 0.0f);
        h1[i] = fmaxf(fmaf((a1[i] - mu) * rs, gh, bh), 0.0f);
        g_h[(n0 + i) * HDIM + lane]      = h0[i];
        g_h[(n0 + i) * HDIM + 32 + lane] = h1[i];
    }
    float acc[4];
#pragma unroll
    for (int i = 0; i < 4; i++) acc[i] = __ldg(&b1[lane]);
#pragma unroll
    for (int k = 0; k < 32; k++) {
        float wk = __ldg(&w1[k * HH + lane]);
#pragma unroll
        for (int i = 0; i < 4; i++)
            acc[i] = fmaf(__shfl_sync(FULL, h0[i], k), wk, acc[i]);
    }
#pragma unroll
    for (int k = 0; k < 32; k++) {
        float wk = __ldg(&w1[(32 + k) * HH + lane]);
#pragma unroll
        for (int i = 0; i < 4; i++)
            acc[i] = fmaf(__shfl_sync(FULL, h1[i], k), wk, acc[i]);
    }
    // store p as fp16 pairs: word j/2 of node holds (p[j], p[j+1]); even lanes store
    unsigned* ph = (unsigned*)g_ph4;
#pragma unroll
    for (int i = 0; i < 4; i++) {
        float pr = __shfl_xor_sync(FULL, acc[i], 1);
        if ((lane & 1) == 0)
            ph[(size_t)(n0 + i) * 16 + (lane >> 1)] = pack_half2(acc[i], pr);
    }
    // zero q (fp16, 4 nodes × 4 uint4) and cnt
    if (lane < 16) g_qh4[n0 * 4 + lane] = make_uint4(0, 0, 0, 0);
    if (lane < 4)  g_cnt[n0 + lane] = 0.0f;
}

// ------- edge kernel: 4 threads/edge; fp16 p gather; fp16 v4.f16x2 RED -------
template<bool COUNT>
__global__ __launch_bounds__(256) void edge_kernel(
    const int* __restrict__ ei, const float* __restrict__ ea,
    const float* __restrict__ w1)
{
    int idx = blockIdx.x * blockDim.x + threadIdx.x;
    int e = idx >> 2, q0 = idx & 3;      // thread covers values [8*q0, 8*q0+8)
    if (e >= E_EDGES) return;

    int src = __ldg(&ei[e]);
    int dst = __ldg(&ei[E_EDGES + e]);
    float e0 = __ldg(&ea[e * 3 + 0]);
    float e1 = __ldg(&ea[e * 3 + 1]);
    float e2 = __ldg(&ea[e * 3 + 2]);

    // gather 8 fp16 p values (16B)
    uint4 praw = __ldg(&g_ph4[src * 4 + q0]);
    float2 p01 = unpack_half2(praw.x);
    float2 p23 = unpack_half2(praw.y);
    float2 p45 = unpack_half2(praw.z);
    float2 p67 = unpack_half2(praw.w);
    float p[8] = { p01.x, p01.y, p23.x, p23.y, p45.x, p45.y, p67.x, p67.y };

    const float4* W = (const float4*)(w1 + 64 * HH);
    float v[8];
#pragma unroll
    for (int s = 0; s < 2; s++) {
        int quad = 2 * q0 + s;
        float4 wa = __ldg(&W[quad]);
        float4 wb = __ldg(&W[8 + quad]);
        float4 wc = __ldg(&W[16 + quad]);
        v[4 * s + 0] = fmaxf(fmaf(e2, wc.x, fmaf(e1, wb.x, fmaf(e0, wa.x, p[4 * s + 0]))), 0.0f);
        v[4 * s + 1] = fmaxf(fmaf(e2, wc.y, fmaf(e1, wb.y, fmaf(e0, wa.y, p[4 * s + 1]))), 0.0f);
        v[4 * s + 2] = fmaxf(fmaf(e2, wc.z, fmaf(e1, wb.z, fmaf(e0, wa.z, p[4 * s + 2]))), 0.0f);
        v[4 * s + 3] = fmaxf(fmaf(e2, wc.w, fmaf(e1, wb.w, fmaf(e0, wa.w, p[4 * s + 3]))), 0.0f);
    }
    unsigned u0 = pack_half2(v[0], v[1]);
    unsigned u1 = pack_half2(v[2], v[3]);
    unsigned u2 = pack_half2(v[4], v[5]);
    unsigned u3 = pack_half2(v[6], v[7]);
    __half* qp = (__half*)g_qh4 + (size_t)dst * 32 + 8 * q0;
    red_add_v4_f16x2(qp, u0, u1, u2, u3);

    if (COUNT && q0 == 0) atomicAdd(&g_cnt[dst], 1.0f);
}

// ---- stage-2 + mean + residual + LN; transposed-smem broadcast; LAST fuses heads ----
template<bool LAST>
__global__ __launch_bounds__(256) void node_agg_kernel(
    const float* __restrict__ w2,  const float* __restrict__ b2,
    const float* __restrict__ g,   const float* __restrict__ beta,
    const float* __restrict__ w1n, const float* __restrict__ b1n,
    const float* __restrict__ dw1, const float* __restrict__ db1,
    const float* __restrict__ dw2, const float* __restrict__ db2,
    const float* __restrict__ vw1, const float* __restrict__ vb1,
    const float* __restrict__ vw2, const float* __restrict__ vb2,
    float* __restrict__ out)
{
    __shared__ float sbuf[64 * 36];   // [k][node], stride 36
    int t = threadIdx.x, w = t >> 5, lane = t & 31;
    int n0 = blockIdx.x * 32;
    int rem = N_NODES - n0; if (rem > 32) rem = 32;

    // stage q (fp16 -> fp32) transposed; zero q behind us
    {
        int nl = t >> 3, k0 = (t & 7) << 2;   // 4 halfs (8B) per thread
        float2 f01 = make_float2(0.f, 0.f), f23 = make_float2(0.f, 0.f);
        __half* qp = (__half*)g_qh4 + (size_t)(n0 + nl) * 32 + k0;
        if (nl < rem) {
            uint2 raw = *(uint2*)qp;
            f01 = unpack_half2(raw.x);
            f23 = unpack_half2(raw.y);
            *(uint2*)qp = make_uint2(0, 0);
        }
        sbuf[(k0 + 0) * 36 + nl] = f01.x;
        sbuf[(k0 + 1) * 36 + nl] = f01.y;
        sbuf[(k0 + 2) * 36 + nl] = f23.x;
        sbuf[(k0 + 3) * 36 + nl] = f23.y;
    }
    __syncthreads();

    int nb = w * 4;

    float o0[4] = {0, 0, 0, 0}, o1[4] = {0, 0, 0, 0};
#pragma unroll
    for (int k = 0; k < 32; k++) {
        float4 qv = *(const float4*)&sbuf[k * 36 + nb];
        float wlo = __ldg(&w2[k * HDIM + lane]);
        float whi = __ldg(&w2[k * HDIM + 32 + lane]);
        o0[0] = fmaf(qv.x, wlo, o0[0]); o1[0] = fmaf(qv.x, whi, o1[0]);
        o0[1] = fmaf(qv.y, wlo, o0[1]); o1[1] = fmaf(qv.y, whi, o1[1]);
        o0[2] = fmaf(qv.z, wlo, o0[2]); o1[2] = fmaf(qv.z, whi, o1[2]);
        o0[3] = fmaf(qv.w, wlo, o0[3]); o1[3] = fmaf(qv.w, whi, o1[3]);
    }
    float b2l = __ldg(&b2[lane]),  b2h = __ldg(&b2[32 + lane]);
    float gl  = __ldg(&g[lane]),   gh  = __ldg(&g[lane + 32]);
    float bl  = __ldg(&beta[lane]), bh = __ldg(&beta[lane + 32]);

    float h0[4], h1[4];
#pragma unroll
    for (int i = 0; i < 4; i++) {
        int n = n0 + nb + i;
        bool act = (nb + i) < rem;
        float c   = act ? g_cnt[n] : 0.f;
        float inv = (c > 0.f) ? (1.f / c) : 0.f;
        float has = (c > 0.f) ? 1.f : 0.f;
        float hh0 = act ? g_h[(size_t)n * HDIM + lane] : 0.f;
        float hh1 = act ? g_h[(size_t)n * HDIM + 32 + lane] : 0.f;
        float a0 = hh0 + o0[i] * inv + has * b2l;
        float a1 = hh1 + o1[i] * inv + has * b2h;
        float s1 = a0 + a1, s2 = a0 * a0 + a1 * a1;
#pragma unroll
        for (int o = 16; o; o >>= 1) {
            s1 += __shfl_xor_sync(FULL, s1, o);
            s2 += __shfl_xor_sync(FULL, s2, o);
        }
        float mu  = s1 * (1.f / 64.f);
        float var = s2 * (1.f / 64.f) - mu * mu;
        float rs  = rsqrtf(var + 1e-5f);
        h0[i] = fmaf((a0 - mu) * rs, gl, bl);
        h1[i] = fmaf((a1 - mu) * rs, gh, bh);
        if (!LAST && act) {
            g_h[(size_t)n * HDIM + lane]      = h0[i];
            g_h[(size_t)n * HDIM + 32 + lane] = h1[i];
        }
    }
    __syncthreads();

#pragma unroll
    for (int i = 0; i < 4; i++) {
        sbuf[lane * 36 + nb + i]        = h0[i];
        sbuf[(lane + 32) * 36 + nb + i] = h1[i];
    }
    __syncthreads();

    if (!LAST) {
        float pacc[4];
        float bb = __ldg(&b1n[lane]);
#pragma unroll
        for (int i = 0; i < 4; i++) pacc[i] = bb;
#pragma unroll
        for (int k = 0; k < 64; k++) {
            float4 hv = *(const float4*)&sbuf[k * 36 + nb];
            float wk = __ldg(&w1n[k * HH + lane]);
            pacc[0] = fmaf(hv.x, wk, pacc[0]);
            pacc[1] = fmaf(hv.y, wk, pacc[1]);
            pacc[2] = fmaf(hv.z, wk, pacc[2]);
            pacc[3] = fmaf(hv.w, wk, pacc[3]);
        }
        // store p fp16 pairs (even lanes)
        unsigned* ph = (unsigned*)g_ph4;
#pragma unroll
        for (int i = 0; i < 4; i++) {
            float pr = __shfl_xor_sync(FULL, pacc[i], 1);
            if ((lane & 1) == 0 && (nb + i) < rem)
                ph[(size_t)(n0 + nb + i) * 16 + (lane >> 1)] = pack_half2(pacc[i], pr);
        }
    } else {
        float da[4], va[4];
        float dbi = __ldg(&db1[lane]), vbi = __ldg(&vb1[lane]);
#pragma unroll
        for (int i = 0; i < 4; i++) { da[i] = dbi; va[i] = vbi; }
#pragma unroll
        for (int k = 0; k < 64; k++) {
            float4 hv = *(const float4*)&sbuf[k * 36 + nb];
            float dwk = __ldg(&dw1[k * HH + lane]);
            float vwk = __ldg(&vw1[k * HH + lane]);
            da[0] = fmaf(hv.x, dwk, da[0]); va[0] = fmaf(hv.x, vwk, va[0]);
            da[1] = fmaf(hv.y, dwk, da[1]); va[1] = fmaf(hv.y, vwk, va[1]);
            da[2] = fmaf(hv.z, dwk, da[2]); va[2] = fmaf(hv.z, vwk, va[2]);
            da[3] = fmaf(hv.w, dwk, da[3]); va[3] = fmaf(hv.w, vwk, va[3]);
        }
        float w2d  = __ldg(&dw2[lane]);
        float w2v0 = __ldg(&vw2[lane * 2 + 0]);
        float w2v1 = __ldg(&vw2[lane * 2 + 1]);
#pragma unroll
        for (int i = 0; i < 4; i++) {
            float rd = fmaxf(da[i], 0.f), rv = fmaxf(va[i], 0.f);
            float d  = rd * w2d;
            float v0 = rv * w2v0;
            float v1 = rv * w2v1;
#pragma unroll
            for (int o = 16; o; o >>= 1) {
                d  += __shfl_xor_sync(FULL, d, o);
                v0 += __shfl_xor_sync(FULL, v0, o);
                v1 += __shfl_xor_sync(FULL, v1, o);
            }
            int n = n0 + nb + i;
            if (lane == 0 && (nb + i) < rem) {
                out[n] = d + __ldg(&db2[0]);
                float2* vout = (float2*)(out + N_NODES);
                vout[n] = make_float2(v0 + __ldg(&vb2[0]), v1 + __ldg(&vb2[1]));
            }
        }
    }
}

// ---------------- launch ----------------
extern "C" void kernel_launch(void* const* d_in, const int* in_sizes, int n_in,
                              void* d_out, int out_size)
{
    const float* x       = (const float*)d_in[0];
    const int*   ei      = (const int*)  d_in[1];
    const float* ea      = (const float*)d_in[2];
    const float* enc_w   = (const float*)d_in[3];
    const float* enc_b   = (const float*)d_in[4];
    const float* enc_g   = (const float*)d_in[5];
    const float* enc_bt  = (const float*)d_in[6];
    const float* mlp_w1  = (const float*)d_in[7];   // [L, 67, 32]
    const float* mlp_b1  = (const float*)d_in[8];   // [L, 32]
    const float* mlp_w2  = (const float*)d_in[9];   // [L, 32, 64]
    const float* mlp_b2  = (const float*)d_in[10];  // [L, 64]
    const float* ln_g    = (const float*)d_in[11];  // [L, 64]
    const float* ln_b    = (const float*)d_in[12];  // [L, 64]
    const float* dw1     = (const float*)d_in[13];
    const float* db1     = (const float*)d_in[14];
    const float* dw2     = (const float*)d_in[15];
    const float* db2     = (const float*)d_in[16];
    const float* vw1     = (const float*)d_in[17];
    const float* vb1     = (const float*)d_in[18];
    const float* vw2     = (const float*)d_in[19];
    const float* vb2     = (const float*)d_in[20];
    float* out = (float*)d_out;

    const int TB = 256;
    const int enc_grid  = (N_NODES / 4 * 32 + TB - 1) / TB;   // 4 nodes/warp
    const int node_grid = (N_NODES + 31) / 32;                // 32 nodes/block
    const int edge_grid = (E_EDGES * 4 + TB - 1) / TB;        // 4 threads/edge

    encoder_kernel<<<enc_grid, TB>>>(x, enc_w, enc_b, enc_g, enc_bt,
                                     mlp_w1, mlp_b1);

    for (int i = 0; i < NLAYERS; i++) {
        const float* w1 = mlp_w1 + (size_t)i * (HDIM + 3) * HH;
        const float* w2 = mlp_w2 + (size_t)i * HH * HDIM;
        const float* b2 = mlp_b2 + (size_t)i * HDIM;
        const float* lg = ln_g   + (size_t)i * HDIM;
        const float* lb = ln_b   + (size_t)i * HDIM;
        const float* w1n = mlp_w1 + (size_t)(i + 1) * (HDIM + 3) * HH;
        const float* b1n = mlp_b1 + (size_t)(i + 1) * HH;

        if (i == 0) edge_kernel<true ><<<edge_grid, TB>>>(ei, ea, w1);
        else        edge_kernel<false><<<edge_grid, TB>>>(ei, ea, w1);

        if (i + 1 < NLAYERS)
            node_agg_kernel<false><<<node_grid, TB>>>(w2, b2, lg, lb, w1n, b1n,
                dw1, db1, dw2, db2, vw1, vb1, vw2, vb2, out);
        else
            node_agg_kernel<true ><<<node_grid, TB>>>(w2, b2, lg, lb, nullptr, nullptr,
                dw1, db1, dw2, db2, vw1, vb1, vw2, vb2, out);
    }
}

// round 14
// speedup vs baseline: 1.6797x; 1.2378x over previous
#include <cuda_runtime.h>
#include <cuda_fp16.h>

#define N_NODES 50000
#define N_TILES 3125         // 16 nodes per mma tile (50000 = 16*3125 exactly)
#define E_EDGES 800000
#define IN_C    16
#define HDIM    64
#define HH      32
#define NLAYERS 3
#define FULL    0xffffffffu

// Scratch (device globals)
__device__ float4 g_hf[N_TILES * 512];   // h in mma-fragment layout: [tile][lane][8 float4]
__device__ uint4  g_ph4[N_NODES * 4];    // p fp16 row-major [n][32] (64B/node)
__device__ uint4  g_qh4[N_NODES * 4];    // q fp16 row-major [n][32] (64B/node)
__device__ float  g_cnt[N_NODES];

// fp16 B-operand fragments, packed once per run
__device__ uint2 g_w2f[NLAYERS * 16 * 32];  // stage-2: [l][(j*2+s)][lane]
__device__ uint2 g_w1f[NLAYERS * 16 * 32];  // p-next:  [l][(jn*4+s)][lane]
__device__ uint2 g_dw1f[16 * 32];
__device__ uint2 g_vw1f[16 * 32];

__device__ __forceinline__ unsigned pack_half2(float lo, float hi) {
    __half2 h = __floats2half2_rn(lo, hi);
    return *reinterpret_cast<unsigned*>(&h);
}
__device__ __forceinline__ float2 unpack_half2(unsigned u) {
    return __half22float2(*reinterpret_cast<__half2*>(&u));
}
__device__ __forceinline__ void red_add_v4_f16x2(__half* ptr, unsigned a, unsigned b,
                                                 unsigned c, unsigned d) {
    asm volatile("red.global.add.noftz.v4.f16x2 [%0], {%1,%2,%3,%4};"
                 :: "l"(ptr), "r"(a), "r"(b), "r"(c), "r"(d) : "memory");
}
__device__ __forceinline__ void hmma(float* c, const unsigned* a, unsigned b0, unsigned b1) {
    asm volatile("mma.sync.aligned.m16n8k16.row.col.f32.f16.f16.f32 "
                 "{%0,%1,%2,%3}, {%4,%5,%6,%7}, {%8,%9}, {%0,%1,%2,%3};"
                 : "+f"(c[0]), "+f"(c[1]), "+f"(c[2]), "+f"(c[3])
                 : "r"(a[0]), "r"(a[1]), "r"(a[2]), "r"(a[3]), "r"(b0), "r"(b1));
}
__device__ __forceinline__ void ldmx4(unsigned* r, unsigned addr) {
    asm volatile("ldmatrix.sync.aligned.m8n8.x4.shared.b16 {%0,%1,%2,%3}, [%4];"
                 : "=r"(r[0]), "=r"(r[1]), "=r"(r[2]), "=r"(r[3]) : "r"(addr));
}

// ---------------- weight fragment pack (once per run) ----------------
__global__ void pack_kernel(const float* __restrict__ mlp_w1,
                            const float* __restrict__ mlp_w2,
                            const float* __restrict__ dw1,
                            const float* __restrict__ vw1)
{
    int idx = blockIdx.x * blockDim.x + threadIdx.x;
    if (idx >= 128 * 32) return;
    int lane = idx & 31, frag = idx >> 5;
    int g = lane >> 2, t = lane & 3;

    if (frag < 48) {               // w2f: frag = (l*8+j)*2+s ; B = W2[32x64], ntile j, kstep s
        int s = frag & 1, rest = frag >> 1, j = rest & 7, l = rest >> 3;
        const float* W = mlp_w2 + (size_t)l * 32 * 64;
        int n = 8 * j + g, k0 = 16 * s;
        g_w2f[idx] = make_uint2(
            pack_half2(W[(k0 + 2 * t) * 64 + n],     W[(k0 + 2 * t + 1) * 64 + n]),
            pack_half2(W[(k0 + 8 + 2 * t) * 64 + n], W[(k0 + 9 + 2 * t) * 64 + n]));
    } else if (frag < 96) {        // w1f: f = (l*4+jn)*4+s ; B = W1[:64][32]
        int f = frag - 48;
        int s = f & 3, rest = f >> 2, jn = rest & 3, l = rest >> 2;
        const float* W = mlp_w1 + (size_t)l * 67 * 32;
        int n = 8 * jn + g, k0 = 16 * s;
        g_w1f[f * 32 + lane] = make_uint2(
            pack_half2(W[(k0 + 2 * t) * 32 + n],     W[(k0 + 2 * t + 1) * 32 + n]),
            pack_half2(W[(k0 + 8 + 2 * t) * 32 + n], W[(k0 + 9 + 2 * t) * 32 + n]));
    } else if (frag < 112) {       // dw1f
        int f = frag - 96;
        int s = f & 3, jn = f >> 2;
        int n = 8 * jn + g, k0 = 16 * s;
        g_dw1f[f * 32 + lane] = make_uint2(
            pack_half2(dw1[(k0 + 2 * t) * 32 + n],     dw1[(k0 + 2 * t + 1) * 32 + n]),
            pack_half2(dw1[(k0 + 8 + 2 * t) * 32 + n], dw1[(k0 + 9 + 2 * t) * 32 + n]));
    } else {                       // vw1f
        int f = frag - 112;
        int s = f & 3, jn = f >> 2;
        int n = 8 * jn + g, k0 = 16 * s;
        g_vw1f[f * 32 + lane] = make_uint2(
            pack_half2(vw1[(k0 + 2 * t) * 32 + n],     vw1[(k0 + 2 * t + 1) * 32 + n]),
            pack_half2(vw1[(k0 + 8 + 2 * t) * 32 + n], vw1[(k0 + 9 + 2 * t) * 32 + n]));
    }
}

// ---------------- encoder: h (fragment layout) + p0(fp16) + zero q/cnt ----------------
__global__ __launch_bounds__(256) void encoder_kernel(
    const float* __restrict__ x,  const float* __restrict__ w,
    const float* __restrict__ b,  const float* __restrict__ g,
    const float* __restrict__ beta,
    const float* __restrict__ w1, const float* __restrict__ b1)
{
    __shared__ float hstage[32][68];
    int wl   = threadIdx.x >> 5;
    int lane = threadIdx.x & 31;
    int n0   = blockIdx.x * 32 + wl * 4;
    bool act = (n0 < N_NODES);

    float h0[4], h1[4];
    if (act) {
        float xv[4], a0[4], a1[4];
#pragma unroll
        for (int i = 0; i < 4; i++) {
            xv[i] = (lane < IN_C) ? x[(n0 + i) * IN_C + lane] : 0.0f;
            a0[i] = __ldg(&b[lane]);
            a1[i] = __ldg(&b[lane + 32]);
        }
#pragma unroll
        for (int k = 0; k < IN_C; k++) {
            float w0 = __ldg(&w[k * HDIM + lane]);
            float w1v = __ldg(&w[k * HDIM + 32 + lane]);
#pragma unroll
            for (int i = 0; i < 4; i++) {
                float xk = __shfl_sync(FULL, xv[i], k);
                a0[i] = fmaf(xk, w0, a0[i]);
                a1[i] = fmaf(xk, w1v, a1[i]);
            }
        }
        float gl = __ldg(&g[lane]), gh = __ldg(&g[lane + 32]);
        float bl = __ldg(&beta[lane]), bh = __ldg(&beta[lane + 32]);
#pragma unroll
        for (int i = 0; i < 4; i++) {
            float s1 = a0[i] + a1[i], s2 = a0[i] * a0[i] + a1[i] * a1[i];
#pragma unroll
            for (int o = 16; o; o >>= 1) {
                s1 += __shfl_xor_sync(FULL, s1, o);
                s2 += __shfl_xor_sync(FULL, s2, o);
            }
            float mu  = s1 * (1.0f / 64.0f);
            float var = s2 * (1.0f / 64.0f) - mu * mu;
            float rs  = rsqrtf(var + 1e-5f);
            h0[i] = fmaxf(fmaf((a0[i] - mu) * rs, gl, bl), 0.0f);
            h1[i] = fmaxf(fmaf((a1[i] - mu) * rs, gh, bh), 0.0f);
            hstage[wl * 4 + i][lane]      = h0[i];
            hstage[wl * 4 + i][lane + 32] = h1[i];
        }
        // p0 = h @ W1[:64] + b1 (fp32 shuffle GEMV, store fp16)
        float acc[4];
#pragma unroll
        for (int i = 0; i < 4; i++) acc[i] = __ldg(&b1[lane]);
#pragma unroll
        for (int k = 0; k < 32; k++) {
            float wk = __ldg(&w1[k * HH + lane]);
#pragma unroll
            for (int i = 0; i < 4; i++)
                acc[i] = fmaf(__shfl_sync(FULL, h0[i], k), wk, acc[i]);
        }
#pragma unroll
        for (int k = 0; k < 32; k++) {
            float wk = __ldg(&w1[(32 + k) * HH + lane]);
#pragma unroll
            for (int i = 0; i < 4; i++)
                acc[i] = fmaf(__shfl_sync(FULL, h1[i], k), wk, acc[i]);
        }
        unsigned* ph = (unsigned*)g_ph4;
#pragma unroll
        for (int i = 0; i < 4; i++) {
            float pr = __shfl_xor_sync(FULL, acc[i], 1);
            if ((lane & 1) == 0)
                ph[(size_t)(n0 + i) * 16 + (lane >> 1)] = pack_half2(acc[i], pr);
        }
        if (lane < 16) g_qh4[(n0 - wl * 4 + wl * 4) * 4 + lane] = make_uint4(0, 0, 0, 0); // q zero (4 nodes*4)
        if (lane < 4)  g_cnt[n0 + lane] = 0.0f;
    }
    __syncthreads();

    // warps 0,1 write the two 16-node tiles in fragment layout
    if (wl < 2) {
        int tile = blockIdx.x * 2 + wl;
        if (tile < N_TILES) {
            int gq = lane >> 2, tq = lane & 3;
            int r0 = wl * 16 + gq, r1 = r0 + 8;
            float4* hfo = g_hf + (size_t)tile * 512 + lane * 8;
#pragma unroll
            for (int j = 0; j < 8; j++) {
                float2 lo = *(float2*)&hstage[r0][2 * tq + 8 * j];
                float2 hi = *(float2*)&hstage[r1][2 * tq + 8 * j];
                hfo[j] = make_float4(lo.x, lo.y, hi.x, hi.y);
            }
        }
    }
}

// ------- edge kernel: 4 threads/edge; fp16 p gather; fp16 v4.f16x2 RED -------
template<bool COUNT>
__global__ __launch_bounds__(256) void edge_kernel(
    const int* __restrict__ ei, const float* __restrict__ ea,
    const float* __restrict__ w1)
{
    int idx = blockIdx.x * blockDim.x + threadIdx.x;
    int e = idx >> 2, q0 = idx & 3;
    if (e >= E_EDGES) return;

    int src = __ldg(&ei[e]);
    int dst = __ldg(&ei[E_EDGES + e]);
    float e0 = __ldg(&ea[e * 3 + 0]);
    float e1 = __ldg(&ea[e * 3 + 1]);
    float e2 = __ldg(&ea[e * 3 + 2]);

    uint4 praw = __ldg(&g_ph4[src * 4 + q0]);
    float2 p01 = unpack_half2(praw.x);
    float2 p23 = unpack_half2(praw.y);
    float2 p45 = unpack_half2(praw.z);
    float2 p67 = unpack_half2(praw.w);
    float p[8] = { p01.x, p01.y, p23.x, p23.y, p45.x, p45.y, p67.x, p67.y };

    const float4* W = (const float4*)(w1 + 64 * HH);
    float v[8];
#pragma unroll
    for (int s = 0; s < 2; s++) {
        int quad = 2 * q0 + s;
        float4 wa = __ldg(&W[quad]);
        float4 wb = __ldg(&W[8 + quad]);
        float4 wc = __ldg(&W[16 + quad]);
        v[4 * s + 0] = fmaxf(fmaf(e2, wc.x, fmaf(e1, wb.x, fmaf(e0, wa.x, p[4 * s + 0]))), 0.0f);
        v[4 * s + 1] = fmaxf(fmaf(e2, wc.y, fmaf(e1, wb.y, fmaf(e0, wa.y, p[4 * s + 1]))), 0.0f);
        v[4 * s + 2] = fmaxf(fmaf(e2, wc.z, fmaf(e1, wb.z, fmaf(e0, wa.z, p[4 * s + 2]))), 0.0f);
        v[4 * s + 3] = fmaxf(fmaf(e2, wc.w, fmaf(e1, wb.w, fmaf(e0, wa.w, p[4 * s + 3]))), 0.0f);
    }
    unsigned u0 = pack_half2(v[0], v[1]);
    unsigned u1 = pack_half2(v[2], v[3]);
    unsigned u2 = pack_half2(v[4], v[5]);
    unsigned u3 = pack_half2(v[6], v[7]);
    __half* qp = (__half*)g_qh4 + (size_t)dst * 32 + 8 * q0;
    red_add_v4_f16x2(qp, u0, u1, u2, u3);

    if (COUNT && q0 == 0) atomicAdd(&g_cnt[dst], 1.0f);
}

// ---- node_agg via HMMA: warp = 16-node tile; stage-2 mma + LN + p-next mma / heads ----
template<bool LAST>
__global__ __launch_bounds__(256) void node_agg_kernel(
    int layer,
    const float* __restrict__ b2,  const float* __restrict__ lng,
    const float* __restrict__ lnb, const float* __restrict__ b1n,
    const float* __restrict__ db1, const float* __restrict__ dw2,
    const float* __restrict__ db2, const float* __restrict__ vb1,
    const float* __restrict__ vw2, const float* __restrict__ vb2,
    float* __restrict__ out)
{
    __shared__ __align__(16) char qs[8][1280];   // per-warp 16 rows x 80B (64B q + 16B pad)
    int tid = threadIdx.x, w = tid >> 5, lane = tid & 31;
    int tile = blockIdx.x * 8 + w;
    if (tile >= N_TILES) return;
    int n0 = tile * 16;
    int g = lane >> 2, tq = lane & 3;

    // stage q fp16 into smem; zero q behind us
    {
        int nl = lane >> 1, half = lane & 1;
        uint4* src = (uint4*)g_qh4 + (size_t)(n0 + nl) * 4 + half * 2;
        uint4 v0 = src[0], v1 = src[1];
        src[0] = make_uint4(0, 0, 0, 0);
        src[1] = make_uint4(0, 0, 0, 0);
        *(uint4*)(qs[w] + nl * 80 + half * 32)      = v0;
        *(uint4*)(qs[w] + nl * 80 + half * 32 + 16) = v1;
    }
    __syncwarp();

    unsigned A0[4], A1[4];
    {
        unsigned base = (unsigned)__cvta_generic_to_shared(qs[w]);
        unsigned addr = base + (lane & 15) * 80 + ((lane >> 4) & 1) * 16;
        ldmx4(A0, addr);        // k halfs 0-15
        ldmx4(A1, addr + 32);   // k halfs 16-31
    }

    // stage-2: o[16x64] = q @ W2
    float acc[8][4];
#pragma unroll
    for (int j = 0; j < 8; j++) { acc[j][0] = acc[j][1] = acc[j][2] = acc[j][3] = 0.f; }
    const uint2* w2f = g_w2f + (size_t)layer * 16 * 32;
#pragma unroll
    for (int j = 0; j < 8; j++) {
        uint2 B0 = __ldg(&w2f[(j * 2 + 0) * 32 + lane]);
        uint2 B1 = __ldg(&w2f[(j * 2 + 1) * 32 + lane]);
        hmma(acc[j], A0, B0.x, B0.y);
        hmma(acc[j], A1, B1.x, B1.y);
    }

    float c0 = __ldg(&g_cnt[n0 + g]),     c1 = __ldg(&g_cnt[n0 + 8 + g]);
    float inv0 = (c0 > 0.f) ? (1.f / c0) : 0.f, has0 = (c0 > 0.f) ? 1.f : 0.f;
    float inv1 = (c1 > 0.f) ? (1.f / c1) : 0.f, has1 = (c1 > 0.f) ? 1.f : 0.f;

    const float2* b22 = (const float2*)b2;
    const float4* hf  = g_hf + (size_t)tile * 512 + lane * 8;
    float s10 = 0.f, s20 = 0.f, s11 = 0.f, s21 = 0.f;
#pragma unroll
    for (int j = 0; j < 8; j++) {
        float4 hp = __ldg(&hf[j]);
        float2 bb = __ldg(&b22[tq + 4 * j]);
        acc[j][0] = hp.x + acc[j][0] * inv0 + has0 * bb.x;
        acc[j][1] = hp.y + acc[j][1] * inv0 + has0 * bb.y;
        acc[j][2] = hp.z + acc[j][2] * inv1 + has1 * bb.x;
        acc[j][3] = hp.w + acc[j][3] * inv1 + has1 * bb.y;
        s10 += acc[j][0] + acc[j][1];
        s20 = fmaf(acc[j][0], acc[j][0], fmaf(acc[j][1], acc[j][1], s20));
        s11 += acc[j][2] + acc[j][3];
        s21 = fmaf(acc[j][2], acc[j][2], fmaf(acc[j][3], acc[j][3], s21));
    }
    s10 += __shfl_xor_sync(FULL, s10, 1); s10 += __shfl_xor_sync(FULL, s10, 2);
    s20 += __shfl_xor_sync(FULL, s20, 1); s20 += __shfl_xor_sync(FULL, s20, 2);
    s11 += __shfl_xor_sync(FULL, s11, 1); s11 += __shfl_xor_sync(FULL, s11, 2);
    s21 += __shfl_xor_sync(FULL, s21, 1); s21 += __shfl_xor_sync(FULL, s21, 2);
    float mu0 = s10 * (1.f / 64.f), var0 = s20 * (1.f / 64.f) - mu0 * mu0;
    float mu1 = s11 * (1.f / 64.f), var1 = s21 * (1.f / 64.f) - mu1 * mu1;
    float rs0 = rsqrtf(var0 + 1e-5f), rs1 = rsqrtf(var1 + 1e-5f);

    const float2* lg2 = (const float2*)lng;
    const float2* lb2 = (const float2*)lnb;
    float4* hfo = g_hf + (size_t)tile * 512 + lane * 8;
    unsigned Ah[4][4];
#pragma unroll
    for (int j = 0; j < 8; j++) {
        float2 gg = __ldg(&lg2[tq + 4 * j]);
        float2 bb = __ldg(&lb2[tq + 4 * j]);
        float v0 = fmaf((acc[j][0] - mu0) * rs0, gg.x, bb.x);
        float v1 = fmaf((acc[j][1] - mu0) * rs0, gg.y, bb.y);
        float v2 = fmaf((acc[j][2] - mu1) * rs1, gg.x, bb.x);
        float v3 = fmaf((acc[j][3] - mu1) * rs1, gg.y, bb.y);
        if (!LAST) hfo[j] = make_float4(v0, v1, v2, v3);
        if ((j & 1) == 0) {
            Ah[j >> 1][0] = pack_half2(v0, v1);
            Ah[j >> 1][1] = pack_half2(v2, v3);
        } else {
            Ah[j >> 1][2] = pack_half2(v0, v1);
            Ah[j >> 1][3] = pack_half2(v2, v3);
        }
    }

    if (!LAST) {
        // p_next[16x32] = h @ W1n + b1n  (store fp16 row-major)
        const uint2* w1f = g_w1f + (size_t)(layer + 1) * 16 * 32;
        const float2* b1n2 = (const float2*)b1n;
        unsigned* ph = (unsigned*)g_ph4;
#pragma unroll
        for (int jn = 0; jn < 4; jn++) {
            float p[4] = {0.f, 0.f, 0.f, 0.f};
#pragma unroll
            for (int s = 0; s < 4; s++) {
                uint2 B = __ldg(&w1f[(jn * 4 + s) * 32 + lane]);
                hmma(p, Ah[s], B.x, B.y);
            }
            float2 bb = __ldg(&b1n2[tq + 4 * jn]);
            ph[(size_t)(n0 + g) * 16 + tq + 4 * jn]     = pack_half2(p[0] + bb.x, p[1] + bb.y);
            ph[(size_t)(n0 + 8 + g) * 16 + tq + 4 * jn] = pack_half2(p[2] + bb.x, p[3] + bb.y);
        }
    } else {
        // heads
        const float2* db12 = (const float2*)db1;
        const float2* vb12 = (const float2*)vb1;
        const float2* dw22 = (const float2*)dw2;
        const float4* vw24 = (const float4*)vw2;
        float ds0 = 0.f, ds1 = 0.f, v00 = 0.f, v01 = 0.f, v10 = 0.f, v11 = 0.f;
#pragma unroll
        for (int jn = 0; jn < 4; jn++) {
            float dh[4] = {0.f, 0.f, 0.f, 0.f}, vh[4] = {0.f, 0.f, 0.f, 0.f};
#pragma unroll
            for (int s = 0; s < 4; s++) {
                uint2 Bd = __ldg(&g_dw1f[(jn * 4 + s) * 32 + lane]);
                uint2 Bv = __ldg(&g_vw1f[(jn * 4 + s) * 32 + lane]);
                hmma(dh, Ah[s], Bd.x, Bd.y);
                hmma(vh, Ah[s], Bv.x, Bv.y);
            }
            float2 dbb = __ldg(&db12[tq + 4 * jn]);
            float2 vbb = __ldg(&vb12[tq + 4 * jn]);
            float r0 = fmaxf(dh[0] + dbb.x, 0.f), r1 = fmaxf(dh[1] + dbb.y, 0.f);
            float r2 = fmaxf(dh[2] + dbb.x, 0.f), r3 = fmaxf(dh[3] + dbb.y, 0.f);
            float2 ww = __ldg(&dw22[tq + 4 * jn]);
            ds0 = fmaf(r0, ww.x, fmaf(r1, ww.y, ds0));
            ds1 = fmaf(r2, ww.x, fmaf(r3, ww.y, ds1));
            float q0v = fmaxf(vh[0] + vbb.x, 0.f), q1v = fmaxf(vh[1] + vbb.y, 0.f);
            float q2v = fmaxf(vh[2] + vbb.x, 0.f), q3v = fmaxf(vh[3] + vbb.y, 0.f);
            float4 vv = __ldg(&vw24[tq + 4 * jn]);   // [c][0],[c][1],[c+1][0],[c+1][1]
            v00 = fmaf(q0v, vv.x, fmaf(q1v, vv.z, v00));
            v01 = fmaf(q0v, vv.y, fmaf(q1v, vv.w, v01));
            v10 = fmaf(q2v, vv.x, fmaf(q3v, vv.z, v10));
            v11 = fmaf(q2v, vv.y, fmaf(q3v, vv.w, v11));
        }
        ds0 += __shfl_xor_sync(FULL, ds0, 1); ds0 += __shfl_xor_sync(FULL, ds0, 2);
        ds1 += __shfl_xor_sync(FULL, ds1, 1); ds1 += __shfl_xor_sync(FULL, ds1, 2);
        v00 += __shfl_xor_sync(FULL, v00, 1); v00 += __shfl_xor_sync(FULL, v00, 2);
        v01 += __shfl_xor_sync(FULL, v01, 1); v01 += __shfl_xor_sync(FULL, v01, 2);
        v10 += __shfl_xor_sync(FULL, v10, 1); v10 += __shfl_xor_sync(FULL, v10, 2);
        v11 += __shfl_xor_sync(FULL, v11, 1); v11 += __shfl_xor_sync(FULL, v11, 2);
        if (tq == 0) {
            float d2 = __ldg(&db2[0]);
            float vb0 = __ldg(&vb2[0]), vb1v = __ldg(&vb2[1]);
            out[n0 + g]     = ds0 + d2;
            out[n0 + 8 + g] = ds1 + d2;
            float2* vout = (float2*)(out + N_NODES);
            vout[n0 + g]     = make_float2(v00 + vb0, v01 + vb1v);
            vout[n0 + 8 + g] = make_float2(v10 + vb0, v11 + vb1v);
        }
    }
}

// ---------------- launch ----------------
extern "C" void kernel_launch(void* const* d_in, const int* in_sizes, int n_in,
                              void* d_out, int out_size)
{
    const float* x       = (const float*)d_in[0];
    const int*   ei      = (const int*)  d_in[1];
    const float* ea      = (const float*)d_in[2];
    const float* enc_w   = (const float*)d_in[3];
    const float* enc_b   = (const float*)d_in[4];
    const float* enc_g   = (const float*)d_in[5];
    const float* enc_bt  = (const float*)d_in[6];
    const float* mlp_w1  = (const float*)d_in[7];   // [L, 67, 32]
    const float* mlp_b1  = (const float*)d_in[8];   // [L, 32]
    const float* mlp_w2  = (const float*)d_in[9];   // [L, 32, 64]
    const float* mlp_b2  = (const float*)d_in[10];  // [L, 64]
    const float* ln_g    = (const float*)d_in[11];  // [L, 64]
    const float* ln_b    = (const float*)d_in[12];  // [L, 64]
    const float* dw1     = (const float*)d_in[13];
    const float* db1     = (const float*)d_in[14];
    const float* dw2     = (const float*)d_in[15];
    const float* db2     = (const float*)d_in[16];
    const float* vw1     = (const float*)d_in[17];
    const float* vb1     = (const float*)d_in[18];
    const float* vw2     = (const float*)d_in[19];
    const float* vb2     = (const float*)d_in[20];
    float* out = (float*)d_out;

    const int TB = 256;
    const int enc_grid  = (N_NODES + 31) / 32;                // 32 nodes/block
    const int node_grid = (N_TILES + 7) / 8;                  // 8 tiles/block
    const int edge_grid = (E_EDGES * 4 + TB - 1) / TB;        // 4 threads/edge

    pack_kernel<<<16, TB>>>(mlp_w1, mlp_w2, dw1, vw1);
    encoder_kernel<<<enc_grid, TB>>>(x, enc_w, enc_b, enc_g, enc_bt,
                                     mlp_w1, mlp_b1);

    for (int i = 0; i < NLAYERS; i++) {
        const float* w1 = mlp_w1 + (size_t)i * (HDIM + 3) * HH;
        const float* b2 = mlp_b2 + (size_t)i * HDIM;
        const float* lg = ln_g   + (size_t)i * HDIM;
        const float* lb = ln_b   + (size_t)i * HDIM;
        const float* b1n = mlp_b1 + (size_t)(i + 1) * HH;

        if (i == 0) edge_kernel<true ><<<edge_grid, TB>>>(ei, ea, w1);
        else        edge_kernel<false><<<edge_grid, TB>>>(ei, ea, w1);

        if (i + 1 < NLAYERS)
            node_agg_kernel<false><<<node_grid, TB>>>(i, b2, lg, lb, b1n,
                db1, dw2, db2, vb1, vw2, vb2, out);
        else
            node_agg_kernel<true ><<<node_grid, TB>>>(i, b2, lg, lb, nullptr,
                db1, dw2, db2, vb1, vw2, vb2, out);
    }
}